// round 16
// baseline (speedup 1.0000x reference)
#include <cuda_runtime.h>
#include <cuda_fp16.h>
#include <math.h>
#include <stdint.h>

#define BB 2
#define CC 256
#define HWN 6400
#define DD 32
#define PP 9

// ---------------- device scratch ----------------
__device__ float g_qn [BB*DD*HWN];        // [b][d][i]  (maxw A operand)
__device__ float g_qnr[BB*HWN*DD];        // [b][n][d]  (topk q rows)
__device__ float g_knr[BB*HWN*DD];        // [b][n][d]  (topk exact k rows, fp32)
__device__ unsigned g_knph[BB*100*16*64]; // per 64-j tile: [pair p(16)][j(64)] h0-pair
__device__ __half g_gmax[(size_t)BB*HWN*800]; // [b][row][tile*8+grp] approx group maxes
__device__ float g_v [BB*HWN*DD];         // [b][j][d]
__device__ float g_pval[BB*HWN*12];       // sorted top9 per row (pad 12)
__device__ int   g_pidx[BB*HWN*12];
__device__ float g_ovb[BB*CC*HWN];        // [b][c][n]
__device__ float g_mlpwT[512*256];        // [k][o], catt1 folded into k>=256

// ---------------- helpers ----------------
__device__ __forceinline__ void mma_f16(
    float& c0, float& c1, float& c2, float& c3,
    unsigned a0, unsigned a1, unsigned a2, unsigned a3,
    unsigned b0, unsigned b1) {
  asm volatile("mma.sync.aligned.m16n8k16.row.col.f32.f16.f16.f32 "
    "{%0,%1,%2,%3},{%4,%5,%6,%7},{%8,%9},{%0,%1,%2,%3};"
    : "+f"(c0), "+f"(c1), "+f"(c2), "+f"(c3)
    : "r"(a0), "r"(a1), "r"(a2), "r"(a3), "r"(b0), "r"(b1));
}
__device__ __forceinline__ void cpa16(void* dst, const void* src) {
  unsigned ds = (unsigned)__cvta_generic_to_shared(dst);
  asm volatile("cp.async.cg.shared.global [%0], [%1], 16;\n" :: "r"(ds), "l"(src));
}
#define CPA_COMMIT() asm volatile("cp.async.commit_group;\n")
#define CPA_WAIT1()  asm volatile("cp.async.wait_group 1;\n")
#define CPA_WAIT0()  asm volatile("cp.async.wait_group 0;\n")

__device__ __forceinline__ void ins9t(float (&mv)[9], int (&mi)[9], float v, int j) {
  if (v > mv[8] || (v == mv[8] && j < mi[8])) {
    float cv = v; int cj = j;
#pragma unroll
    for (int s = 0; s < 9; s++) {
      bool bt = (cv > mv[s]) || (cv == mv[s] && cj < mi[s]);
      float nv = bt ? cv : mv[s]; int ni = bt ? cj : mi[s];
      float ov_ = bt ? mv[s] : cv; int oi = bt ? mi[s] : cj;
      mv[s]=nv; mi[s]=ni; cv=ov_; cj=oi;
    }
  }
}
__device__ __forceinline__ unsigned pkh2(float a, float b) {
  __half ha = __float2half_rn(a), hb = __float2half_rn(b);
  return (unsigned)__half_as_ushort(ha) | ((unsigned)__half_as_ushort(hb) << 16);
}
__device__ __forceinline__ void splith2(float a, float b, unsigned& hi, unsigned& lo) {
  __half ha = __float2half_rn(a), hb = __float2half_rn(b);
  __half la = __float2half_rn(a - __half2float(ha));
  __half lb = __float2half_rn(b - __half2float(hb));
  hi = (unsigned)__half_as_ushort(ha) | ((unsigned)__half_as_ushort(hb) << 16);
  lo = (unsigned)__half_as_ushort(la) | ((unsigned)__half_as_ushort(lb) << 16);
}
__device__ __forceinline__ float h2f_lo(unsigned u) {
  return __half2float(__ushort_as_half((unsigned short)(u & 0xFFFF)));
}
__device__ __forceinline__ float h2f_hi(unsigned u) {
  return __half2float(__ushort_as_half((unsigned short)(u >> 16)));
}

// ---------------- K0: fold catt1 into transposed mlp weights ----------------
__global__ void __launch_bounds__(256) prep_kernel(
    const float* __restrict__ mlp_w, const float* __restrict__ catt1) {
  int i = blockIdx.x*256 + threadIdx.x;
  int o = i >> 9, k = i & 511;
  float v = mlp_w[i];
  if (k >= 256) v *= catt1[k-256];
  g_mlpwT[k*256 + o] = v;
}

// ---------------- K1: projections + L2 normalize + layouts ----------------
__global__ void __launch_bounds__(256) proj_kernel(
    const float* __restrict__ feat, const float* __restrict__ Wq,
    const float* __restrict__ Wk,   const float* __restrict__ Wv) {
  __shared__ float xs[64][33];
  __shared__ float ws[96][64];
  __shared__ float outs[96][33];
  __shared__ float scl[2][32];
  int blk = blockIdx.x;
  int b  = blk / 200;
  int n0 = (blk % 200) * 32;
  int t  = threadIdx.x;
  int n  = t & 31, dg = t >> 5;
  float acc[12];
#pragma unroll
  for (int u = 0; u < 12; u++) acc[u] = 0.f;

  for (int c0 = 0; c0 < CC; c0 += 64) {
#pragma unroll
    for (int r = 0; r < 8; r++) {
      int e = t + 256*r; int cl = e >> 5, nn = e & 31;
      xs[cl][nn] = feat[(b*CC + c0 + cl)*HWN + n0 + nn];
    }
#pragma unroll
    for (int r = 0; r < 24; r++) {
      int e = t + 256*r; int cl = e & 63, d = e >> 6;
      const float* Wp = (d < 32) ? Wq : ((d < 64) ? Wk : Wv);
      ws[d][cl] = Wp[(d & 31)*CC + c0 + cl];
    }
    __syncthreads();
#pragma unroll 4
    for (int cl = 0; cl < 64; cl += 4) {
      float x0 = xs[cl][n], x1 = xs[cl+1][n], x2 = xs[cl+2][n], x3 = xs[cl+3][n];
#pragma unroll
      for (int u = 0; u < 12; u++) {
        const float4 w4 = *(const float4*)&ws[dg*12+u][cl];
        acc[u] += w4.x*x0 + w4.y*x1 + w4.z*x2 + w4.w*x3;
      }
    }
    __syncthreads();
  }
#pragma unroll
  for (int u = 0; u < 12; u++) outs[dg*12+u][n] = acc[u];
  __syncthreads();
  if (t < 64) {
    int nn = t & 31, wh = t >> 5;
    float s = 0.f;
#pragma unroll
    for (int d = 0; d < 32; d++) { float v = outs[wh*32+d][nn]; s += v*v; }
    scl[wh][nn] = 1.f / fmaxf(sqrtf(s), 1e-12f);
  }
  __syncthreads();
#pragma unroll
  for (int r = 0; r < 4; r++) {
    int e = t + 256*r; int d = e & 31, nn = e >> 5;
    int nglob = n0 + nn;
    float qv = outs[d][nn] * scl[0][nn];
    g_qn[(b*DD + d)*HWN + nglob] = qv;
    g_qnr[(size_t)(b*HWN + nglob)*DD + d] = qv;
    float kv = outs[32+d][nn] * scl[1][nn];
    g_knr[(size_t)(b*HWN + nglob)*DD + d] = kv;
    __half h0 = __float2half_rn(kv);
    int T = nglob >> 6, jj = nglob & 63;
    int p = d >> 1, slot = d & 1;
    uint16_t* kp = (uint16_t*)g_knph;
    kp[(size_t)(((b*100 + T)*16 + p)*64 + jj)*2 + slot] = __half_as_ushort(h0);
    g_v[(size_t)(b*HWN + nglob)*DD + d] = outs[64+d][nn];
  }
}

// ---------------- K2a: approx w (hi*hi HMMA) -> per-8-group maxes ----------------
__global__ void __launch_bounds__(128) maxw_kernel() {
  __shared__ float qs[32][72];
  __shared__ unsigned bfs[2][16][72];
  int blk = blockIdx.x;
  int b = blk / 400; int rem = blk % 400;
  int split = rem / 100; int i0 = (rem % 100) * 64;
  int t = threadIdx.x;
  int lane = t & 31, w = t >> 5, g = lane >> 2, t4 = lane & 3;
  int ib = w*16;
  int tile0 = split * 25;
  const unsigned* kf = g_knph + (size_t)(b*100 + tile0)*1024;

#pragma unroll
  for (int r = 0; r < 16; r++) {
    int e = t + 128*r; int i = e & 63, d = e >> 6;
    qs[d][i] = g_qn[(b*DD + d)*HWN + i0 + i];
  }
  __syncthreads();

  unsigned Ah[2][4];
#pragma unroll
  for (int c = 0; c < 2; c++) {
    int kb = c*16 + 2*t4;
#pragma unroll
    for (int r = 0; r < 4; r++) {
      int kk = kb + ((r >= 2) ? 8 : 0);
      int ii = ib + g + ((r & 1) ? 8 : 0);
      Ah[c][r] = pkh2(qs[kk][ii], qs[kk+1][ii]);
    }
  }

#pragma unroll
  for (int r = 0; r < 2; r++) {
    int idx = t + 128*r;
    int row = idx >> 4, c16 = idx & 15;
    cpa16(&bfs[0][row][c16*4], kf + row*64 + c16*4);
  }
  CPA_COMMIT();

  for (int jt = 0; jt < 25; jt++) {
    if (jt + 1 < 25) {
      int nb = (jt+1) & 1;
      const unsigned* src = kf + (size_t)(jt+1)*1024;
#pragma unroll
      for (int r = 0; r < 2; r++) {
        int idx = t + 128*r;
        int row = idx >> 4, c16 = idx & 15;
        cpa16(&bfs[nb][row][c16*4], src + row*64 + c16*4);
      }
      CPA_COMMIT();
      CPA_WAIT1();
    } else {
      CPA_WAIT0();
    }
    __syncthreads();
    const unsigned (*hp)[72] = bfs[jt & 1];

    float Cf[8][4];
#pragma unroll
    for (int nf = 0; nf < 8; nf++)
#pragma unroll
      for (int r = 0; r < 4; r++) Cf[nf][r] = 0.f;

#pragma unroll
    for (int c = 0; c < 2; c++) {
#pragma unroll
      for (int nf = 0; nf < 8; nf++) {
        unsigned p1 = hp[c*8 + t4    ][nf*8 + g];
        unsigned p2 = hp[c*8 + t4 + 4][nf*8 + g];
        mma_f16(Cf[nf][0],Cf[nf][1],Cf[nf][2],Cf[nf][3],
                Ah[c][0],Ah[c][1],Ah[c][2],Ah[c][3], p1, p2);
      }
    }
    float gma[8], gmb[8];
#pragma unroll
    for (int nf = 0; nf < 8; nf++) {
      gma[nf] = fmaxf(Cf[nf][0], Cf[nf][1]);
      gmb[nf] = fmaxf(Cf[nf][2], Cf[nf][3]);
    }
#pragma unroll
    for (int nf = 0; nf < 8; nf++) {
      gma[nf] = fmaxf(gma[nf], __shfl_xor_sync(0xffffffffu, gma[nf], 1));
      gma[nf] = fmaxf(gma[nf], __shfl_xor_sync(0xffffffffu, gma[nf], 2));
      gmb[nf] = fmaxf(gmb[nf], __shfl_xor_sync(0xffffffffu, gmb[nf], 1));
      gmb[nf] = fmaxf(gmb[nf], __shfl_xor_sync(0xffffffffu, gmb[nf], 2));
    }
    if (t4 == 0) {
      int tileg = tile0 + jt;
      uint4 pa, pb;
      pa.x = pkh2(gma[0], gma[1]); pa.y = pkh2(gma[2], gma[3]);
      pa.z = pkh2(gma[4], gma[5]); pa.w = pkh2(gma[6], gma[7]);
      pb.x = pkh2(gmb[0], gmb[1]); pb.y = pkh2(gmb[2], gmb[3]);
      pb.z = pkh2(gmb[4], gmb[5]); pb.w = pkh2(gmb[6], gmb[7]);
      size_t ra = (size_t)(b*HWN + i0 + ib + g)*800 + tileg*8;
      size_t rb = (size_t)(b*HWN + i0 + ib + 8 + g)*800 + tileg*8;
      *(uint4*)&g_gmax[ra] = pa;
      *(uint4*)&g_gmax[rb] = pb;
    }
    __syncthreads();
  }
}

// ---------------- K2b: 2 warps/row exact top-9, shared tau ----------------
// grid 3200 x 256: 8 warps/block = 4 rows/block, warp pair (half 0/1) per row.
__global__ void __launch_bounds__(256) topk_kernel() {
  __shared__ float smv[4][12];
  __shared__ int   smi[4][12];
  __shared__ float stau[4][2];
  __shared__ unsigned short glist[8][400];
  int wid = threadIdx.x >> 5;
  int lane = threadIdx.x & 31;
  int pr = wid >> 1, half = wid & 1;
  int grow = blockIdx.x*4 + pr;
  int b = grow / HWN, row = grow % HWN;
  int cand = lane >> 2, qr = lane & 3;

  float qq[8];
  {
    const float* qp = &g_qnr[(size_t)(b*HWN + row)*DD + qr*8];
    float4 a = *(const float4*)qp;
    float4 c = *(const float4*)(qp+4);
    qq[0]=a.x; qq[1]=a.y; qq[2]=a.z; qq[3]=a.w;
    qq[4]=c.x; qq[5]=c.y; qq[6]=c.z; qq[7]=c.w;
  }

  const __half* gmrow = &g_gmax[(size_t)(b*HWN + row)*800 + half*400];
  uint4 ch[2]; bool has[2];
  float m1 = -4.f, m2 = -4.f, m3 = -4.f;
#pragma unroll
  for (int slot = 0; slot < 2; slot++) {
    int c = slot*32 + lane;
    has[slot] = (c < 50);
    if (has[slot]) {
      ch[slot] = *(const uint4*)&gmrow[c*8];
      const unsigned* u = (const unsigned*)&ch[slot];
#pragma unroll
      for (int hh = 0; hh < 4; hh++) {
        float v0 = h2f_lo(u[hh]), v1 = h2f_hi(u[hh]);
        float tlo = fminf(v0, m1); m1 = fmaxf(v0, m1);
        float ulo = fminf(tlo, m2); m2 = fmaxf(tlo, m2);
        m3 = fmaxf(ulo, m3);
        tlo = fminf(v1, m1); m1 = fmaxf(v1, m1);
        ulo = fminf(tlo, m2); m2 = fmaxf(tlo, m2);
        m3 = fmaxf(ulo, m3);
      }
    }
  }
  // tau_half = 9th largest of union of lane top-3s (subset => conservative)
  float tau = -4.f;
#pragma unroll
  for (int rnd = 0; rnd < 9; rnd++) {
    float wm = m1;
#pragma unroll
    for (int s = 16; s > 0; s >>= 1) wm = fmaxf(wm, __shfl_xor_sync(0xffffffffu, wm, s));
    unsigned bal = __ballot_sync(0xffffffffu, m1 == wm);
    int leader = __ffs(bal) - 1;
    if (lane == leader) { m1 = m2; m2 = m3; m3 = -4.f; }
    tau = wm;
  }
  // share tau across the half-pair: union-9th >= max(tau0, tau1), still a
  // valid lower bound on the row's true 9th group-max, but tighter per half.
  if (lane == 0) stau[pr][half] = tau;
  __syncthreads();
  float thr = fmaxf(stau[pr][0], stau[pr][1]) - 0.002f;

  // build screened group list (uniform; lane 0 stores)
  int cnt = 0;
#pragma unroll
  for (int slot = 0; slot < 2; slot++) {
    unsigned msk = 0;
    if (has[slot]) {
      const unsigned* u = (const unsigned*)&ch[slot];
#pragma unroll
      for (int hh = 0; hh < 4; hh++) {
        if (h2f_lo(u[hh]) >= thr) msk |= 1u << (2*hh);
        if (h2f_hi(u[hh]) >= thr) msk |= 1u << (2*hh+1);
      }
    }
    unsigned lanebal = __ballot_sync(0xffffffffu, msk != 0);
    while (lanebal) {
      int Lb = __ffs(lanebal) - 1; lanebal &= lanebal - 1;
      unsigned gm8 = __shfl_sync(0xffffffffu, msk, Lb);
      int tile = half*50 + slot*32 + Lb;
      while (gm8) {
        int g8 = __ffs(gm8) - 1; gm8 &= gm8 - 1;
        if (lane == 0) glist[wid][cnt] = (unsigned short)(tile*8 + g8);
        cnt++;
      }
    }
  }
  __syncwarp();

  float tv[9]; int ti[9];
#pragma unroll
  for (int s = 0; s < 9; s++) { tv[s] = -4.f; ti[s] = 0x7fffffff; }

  const float* knb = g_knr + (size_t)b*HWN*DD;
  float4 p0, p1;
  if (cnt > 0) {
    int gi0 = glist[wid][0];
    const float* kp = knb + (size_t)(gi0*8 + cand)*DD + qr*8;
    p0 = *(const float4*)kp; p1 = *(const float4*)(kp+4);
  }
  for (int i = 0; i < cnt; i++) {
    float4 c0 = p0, c1 = p1;
    int jb = glist[wid][i]*8;
    if (i + 1 < cnt) {
      int gin = glist[wid][i+1];
      const float* kp = knb + (size_t)(gin*8 + cand)*DD + qr*8;
      p0 = *(const float4*)kp; p1 = *(const float4*)(kp+4);
    }
    float acc = qq[0]*c0.x + qq[1]*c0.y + qq[2]*c0.z + qq[3]*c0.w
              + qq[4]*c1.x + qq[5]*c1.y + qq[6]*c1.z + qq[7]*c1.w;
    acc += __shfl_xor_sync(0xffffffffu, acc, 1);
    acc += __shfl_xor_sync(0xffffffffu, acc, 2);
    float wmax = fmaxf(acc, __shfl_xor_sync(0xffffffffu, acc, 4));
    wmax = fmaxf(wmax, __shfl_xor_sync(0xffffffffu, wmax, 8));
    wmax = fmaxf(wmax, __shfl_xor_sync(0xffffffffu, wmax, 16));
    if (wmax >= tv[8]) {
      unsigned bal = __ballot_sync(0xffffffffu, acc >= tv[8]) & 0x11111111u;
      while (bal) {
        int L = __ffs(bal) - 1; bal &= bal - 1;
        float v = __shfl_sync(0xffffffffu, acc, L);
        ins9t(tv, ti, v, jb + (L >> 2));
      }
    }
  }

  // merge halves: half 1 publishes, half 0 merges + writes
  if (half == 1 && lane == 0) {
#pragma unroll
    for (int s = 0; s < 9; s++) { smv[pr][s] = tv[s]; smi[pr][s] = ti[s]; }
  }
  __syncthreads();
  if (half == 0) {
#pragma unroll
    for (int s = 0; s < 9; s++) ins9t(tv, ti, smv[pr][s], smi[pr][s]);
    if (lane == 0) {
      size_t base = (size_t)(b*HWN + row)*12;
#pragma unroll
      for (int s = 0; s < 9; s++) { g_pval[base+s] = tv[s]; g_pidx[base+s] = ti[s]; }
    }
  }
}

// ---------------- K3: post (single sorted list per row) ----------------
__global__ void __launch_bounds__(256) post_kernel(
    const float* __restrict__ adw, const float* __restrict__ adb,
    const float* __restrict__ pw1, const float* __restrict__ pw2,
    const float* __restrict__ back_w, const float* __restrict__ catt) {
  __shared__ float lv2[32][12];
  __shared__ int   li2[32][12];
  __shared__ float w1s[162];
  __shared__ float w2s[162];
  __shared__ float wfin_s[32][12];
  __shared__ int   idx_s[32][12];
  __shared__ float ovs[32][36];
  int blk = blockIdx.x;
  int b = blk / 200;
  int row0 = (blk % 200) * 32;
  int t = threadIdx.x;

  float4 bw[8];
#pragma unroll
  for (int r = 0; r < 8; r++) bw[r] = *(const float4*)&back_w[t*DD + r*4];
  float cattc = catt[t];
  if (t < 162) { w1s[t] = pw1[t]; w2s[t] = pw2[t]; }

#pragma unroll
  for (int r = 0; r < 2; r++) {
    int e = t + 256*r;
    if (e < 384) {
      int row = e / 12, q = e % 12;
      size_t gbase = (size_t)(b*HWN + row0 + row)*12 + q;
      lv2[row][q] = g_pval[gbase];
      li2[row][q] = g_pidx[gbase];
    }
  }
  __syncthreads();

  if (t < 32) {
    float adwv = adw[0], adbv = adb[0];
    float xa[9], pos[9];
#pragma unroll
    for (int p = 0; p < 9; p++) { xa[p] = lv2[t][p]*adwv + adbv; pos[p] = fmaxf(xa[p], 0.f); }
    float hdn[18];
#pragma unroll
    for (int q = 0; q < 18; q++) {
      float s = 0.f;
#pragma unroll
      for (int p = 0; p < 9; p++) s += w1s[q*9+p]*pos[p];
      hdn[q] = fmaxf(s, 0.f);
    }
    float z[9]; float zmax = -1e30f;
#pragma unroll
    for (int p = 0; p < 9; p++) { z[p] = (xa[p] > 0.f) ? xa[p] : -100000.0f; zmax = fmaxf(zmax, z[p]); }
    float es[9]; float esum = 0.f;
#pragma unroll
    for (int p = 0; p < 9; p++) { es[p] = expf(z[p]-zmax); esum += es[p]; }
    float inv = 1.f/esum;
#pragma unroll
    for (int p = 0; p < 9; p++) {
      float s = 0.f;
#pragma unroll
      for (int q = 0; q < 18; q++) s += w2s[p*18+q]*hdn[q];
      float msk = 1.f/(1.f+expf(-s));
      wfin_s[t][p] = es[p]*inv*msk;
      idx_s[t][p]  = li2[t][p];
    }
  }
  __syncthreads();

  {
    int row = t >> 3, dq = t & 7;
    float4 acc = make_float4(0.f, 0.f, 0.f, 0.f);
#pragma unroll
    for (int p = 0; p < 9; p++) {
      float wv = wfin_s[row][p];
      int j = idx_s[row][p];
      float4 v4 = *(const float4*)&g_v[((size_t)b*HWN + j)*DD + dq*4];
      acc.x += wv*v4.x; acc.y += wv*v4.y; acc.z += wv*v4.z; acc.w += wv*v4.w;
    }
    *(float4*)&ovs[row][dq*4] = acc;
  }
  __syncthreads();

  float* dst = &g_ovb[((size_t)b*CC + t)*HWN + row0];
#pragma unroll
  for (int r4 = 0; r4 < 8; r4++) {
    float4 o4;
    float* o = (float*)&o4;
#pragma unroll
    for (int u = 0; u < 4; u++) {
      int row = r4*4 + u;
      float acc = 0.f;
#pragma unroll
      for (int d4 = 0; d4 < 8; d4++) {
        float4 v4 = *(const float4*)&ovs[row][d4*4];
        acc += bw[d4].x*v4.x + bw[d4].y*v4.y + bw[d4].z*v4.z + bw[d4].w*v4.w;
      }
      o[u] = acc * cattc;
    }
    *(float4*)&dst[r4*4] = o4;
  }
}

// ---------------- K4: mlp GEMM (fp16x3 HMMA m16n8k16, cp.async) ----------------
__global__ void __launch_bounds__(128) mlp_kernel(
    const float* __restrict__ feat, const float* __restrict__ mlp_b,
    const float* __restrict__ mlp_gamma, const float* __restrict__ mlp_beta,
    float* __restrict__ xout) {
  __shared__ float a_s[2][32][72];
  __shared__ float b_s[2][32][72];
  int blk = blockIdx.x;
  int b = blk / 400; int rem = blk % 400;
  int o0 = (rem / 100) * 64;
  int n0 = (rem % 100) * 64;
  int t = threadIdx.x;
  int w = t >> 5, lane = t & 31, g = lane >> 2, t4 = lane & 3;
  int ol = w*16;

  float Cf[8][4];
#pragma unroll
  for (int nf = 0; nf < 8; nf++)
#pragma unroll
    for (int r = 0; r < 4; r++) Cf[nf][r] = 0.f;

  const float* bbase = &g_ovb[(size_t)b*CC*HWN];
  const float* fbase = &feat[(size_t)b*CC*HWN];

#pragma unroll
  for (int r = 0; r < 4; r++) {
    int q = t + 128*r; int kk = q >> 4; int xx = (q & 15)*4;
    cpa16(&a_s[0][kk][xx], &g_mlpwT[kk*256 + o0 + xx]);
    cpa16(&b_s[0][kk][xx], bbase + (size_t)kk*HWN + n0 + xx);
  }
  CPA_COMMIT();

  for (int kt = 0; kt < 16; kt++) {
    if (kt + 1 < 16) {
      int k1 = (kt+1)*32; int buf = (kt+1) & 1;
      const float* srcB = (k1 < 256) ? (bbase + (size_t)k1*HWN)
                                     : (fbase + (size_t)(k1-256)*HWN);
#pragma unroll
      for (int r = 0; r < 4; r++) {
        int q = t + 128*r; int kk = q >> 4; int xx = (q & 15)*4;
        cpa16(&a_s[buf][kk][xx], &g_mlpwT[(k1+kk)*256 + o0 + xx]);
        cpa16(&b_s[buf][kk][xx], srcB + (size_t)kk*HWN + n0 + xx);
      }
      CPA_COMMIT();
      CPA_WAIT1();
    } else {
      CPA_WAIT0();
    }
    __syncthreads();
    int buf = kt & 1;
    const float (*ab)[72] = a_s[buf];
    const float (*bb)[72] = b_s[buf];

#pragma unroll
    for (int c = 0; c < 2; c++) {
      int kb = c*16 + 2*t4;
      unsigned Ah[4], Al[4];
#pragma unroll
      for (int r = 0; r < 4; r++) {
        int kk = kb + ((r >= 2) ? 8 : 0);
        int oo = ol + g + ((r & 1) ? 8 : 0);
        splith2(ab[kk][oo], ab[kk+1][oo], Ah[r], Al[r]);
      }
#pragma unroll
      for (int nf = 0; nf < 8; nf++) {
        int nn = nf*8 + g;
        unsigned Bh0, Bl0, Bh1, Bl1;
        splith2(bb[kb][nn],   bb[kb+1][nn], Bh0, Bl0);
        splith2(bb[kb+8][nn], bb[kb+9][nn], Bh1, Bl1);
        mma_f16(Cf[nf][0],Cf[nf][1],Cf[nf][2],Cf[nf][3],
                Al[0],Al[1],Al[2],Al[3], Bh0,Bh1);
        mma_f16(Cf[nf][0],Cf[nf][1],Cf[nf][2],Cf[nf][3],
                Ah[0],Ah[1],Ah[2],Ah[3], Bl0,Bl1);
        mma_f16(Cf[nf][0],Cf[nf][1],Cf[nf][2],Cf[nf][3],
                Ah[0],Ah[1],Ah[2],Ah[3], Bh0,Bh1);
      }
    }
    __syncthreads();
  }
  const float bnadj = rsqrtf(1.0f + 1e-5f);
  int oa = o0 + ol + g;
  int ob = oa + 8;
  float ga  = mlp_gamma[oa]*bnadj, ba = mlp_beta[oa], mba = mlp_b[oa];
  float gb2 = mlp_gamma[ob]*bnadj, bb2 = mlp_beta[ob], mbb = mlp_b[ob];
#pragma unroll
  for (int nf = 0; nf < 8; nf++) {
    int nc = n0 + nf*8 + 2*t4;
    float2 ra, rb;
    ra.x = fmaxf((Cf[nf][0]+mba)*ga + ba, 0.f);
    ra.y = fmaxf((Cf[nf][1]+mba)*ga + ba, 0.f);
    rb.x = fmaxf((Cf[nf][2]+mbb)*gb2 + bb2, 0.f);
    rb.y = fmaxf((Cf[nf][3]+mbb)*gb2 + bb2, 0.f);
    *(float2*)&xout[((size_t)b*CC + oa)*HWN + nc] = ra;
    *(float2*)&xout[((size_t)b*CC + ob)*HWN + nc] = rb;
  }
}

// ---------------- K5: dsn head ----------------
__global__ void __launch_bounds__(256) dsn_kernel(
    const float* __restrict__ dsn_w, const float* __restrict__ dsn_b,
    const float* __restrict__ dsn_g, const float* __restrict__ dsn_beta,
    const float* __restrict__ x, float* __restrict__ r0) {
  __shared__ float ws[256];
  __shared__ float s2[2][128];
  int blk = blockIdx.x;
  int b  = blk / 50;
  int n0 = (blk % 50) * 128;
  int t  = threadIdx.x;
  ws[t] = dsn_w[t];
  __syncthreads();
  int nl = t & 127, half = t >> 7;
  int n = n0 + nl;
  float acc = 0.f;
  int obase = half*128;
#pragma unroll 8
  for (int o = 0; o < 128; o++) acc += ws[obase+o]*x[(b*CC+obase+o)*HWN + n];
  s2[half][nl] = acc;
  __syncthreads();
  if (t < 128) {
    float a = s2[0][t] + s2[1][t];
    float g = dsn_g[0]*rsqrtf(1.0f+1e-5f);
    r0[b*HWN + n0 + t] = fmaxf((a + dsn_b[0])*g + dsn_beta[0], 0.f);
  }
}

// ---------------- launch ----------------
extern "C" void kernel_launch(void* const* d_in, const int* in_sizes, int n_in,
                              void* d_out, int out_size) {
  const float* feat    = (const float*)d_in[0];
  const float* Wq      = (const float*)d_in[1];
  const float* Wk      = (const float*)d_in[2];
  const float* Wv      = (const float*)d_in[3];
  const float* adw     = (const float*)d_in[4];
  const float* adb     = (const float*)d_in[5];
  const float* pw1     = (const float*)d_in[6];
  const float* pw2     = (const float*)d_in[7];
  const float* backw   = (const float*)d_in[8];
  const float* catt    = (const float*)d_in[9];
  const float* catt1   = (const float*)d_in[10];
  const float* mlpw    = (const float*)d_in[11];
  const float* mlpb    = (const float*)d_in[12];
  const float* mlpg    = (const float*)d_in[13];
  const float* mlpbeta = (const float*)d_in[14];
  const float* dsnw    = (const float*)d_in[15];
  const float* dsnb    = (const float*)d_in[16];
  const float* dsng    = (const float*)d_in[17];
  const float* dsnbeta = (const float*)d_in[18];
  float* out = (float*)d_out;

  // slot 3 (ncu capture) = topk_kernel
  proj_kernel<<<400, 256>>>(feat, Wq, Wk, Wv);
  maxw_kernel<<<800, 128>>>();
  prep_kernel<<<512, 256>>>(mlpw, catt1);
  topk_kernel<<<3200, 256>>>();
  post_kernel<<<400, 256>>>(adw, adb, pw1, pw2, backw, catt);
  mlp_kernel<<<800, 128>>>(feat, mlpb, mlpg, mlpbeta, out);
  dsn_kernel<<<100, 256>>>(dsnw, dsnb, dsng, dsnbeta, out, out + BB*CC*HWN);
}

// round 17
// speedup vs baseline: 1.0627x; 1.0627x over previous
#include <cuda_runtime.h>
#include <cuda_fp16.h>
#include <math.h>
#include <stdint.h>

#define BB 2
#define CC 256
#define HWN 6400
#define DD 32
#define PP 9

// ---------------- device scratch ----------------
__device__ float g_qn [BB*DD*HWN];        // [b][d][i]  (maxw A operand)
__device__ float g_qnr[BB*HWN*DD];        // [b][n][d]  (topk q rows)
__device__ float g_knr[BB*HWN*DD];        // [b][n][d]  (topk exact k rows, fp32)
__device__ unsigned g_knph[BB*100*16*64]; // per 64-j tile: [pair p(16)][j(64)] h0-pair
__device__ __half g_gmax[(size_t)BB*HWN*800]; // [b][row][tile*8+grp] approx group maxes
__device__ float g_v [BB*HWN*DD];         // [b][j][d]
__device__ float g_pval[BB*HWN*12];       // sorted top9 per row (pad 12)
__device__ int   g_pidx[BB*HWN*12];
__device__ float g_ovb[BB*CC*HWN];        // [b][c][n]
__device__ float g_mlpwT[512*256];        // [k][o], catt1 folded into k>=256

// ---------------- helpers ----------------
__device__ __forceinline__ void split2(float v, unsigned& h, unsigned& l) {
  unsigned hv = __float_as_uint(v) & 0xFFFFE000u;
  h = hv;
  l = __float_as_uint(v - __uint_as_float(hv));
}
__device__ __forceinline__ void mma_tf32(
    float& c0, float& c1, float& c2, float& c3,
    unsigned a0, unsigned a1, unsigned a2, unsigned a3,
    unsigned b0, unsigned b1) {
  asm volatile("mma.sync.aligned.m16n8k8.row.col.f32.tf32.tf32.f32 "
    "{%0,%1,%2,%3},{%4,%5,%6,%7},{%8,%9},{%0,%1,%2,%3};"
    : "+f"(c0), "+f"(c1), "+f"(c2), "+f"(c3)
    : "r"(a0), "r"(a1), "r"(a2), "r"(a3), "r"(b0), "r"(b1));
}
__device__ __forceinline__ void mma_f16(
    float& c0, float& c1, float& c2, float& c3,
    unsigned a0, unsigned a1, unsigned a2, unsigned a3,
    unsigned b0, unsigned b1) {
  asm volatile("mma.sync.aligned.m16n8k16.row.col.f32.f16.f16.f32 "
    "{%0,%1,%2,%3},{%4,%5,%6,%7},{%8,%9},{%0,%1,%2,%3};"
    : "+f"(c0), "+f"(c1), "+f"(c2), "+f"(c3)
    : "r"(a0), "r"(a1), "r"(a2), "r"(a3), "r"(b0), "r"(b1));
}
__device__ __forceinline__ void cpa16(void* dst, const void* src) {
  unsigned ds = (unsigned)__cvta_generic_to_shared(dst);
  asm volatile("cp.async.cg.shared.global [%0], [%1], 16;\n" :: "r"(ds), "l"(src));
}
#define CPA_COMMIT() asm volatile("cp.async.commit_group;\n")
#define CPA_WAIT1()  asm volatile("cp.async.wait_group 1;\n")
#define CPA_WAIT0()  asm volatile("cp.async.wait_group 0;\n")

__device__ __forceinline__ void ins9t(float (&mv)[9], int (&mi)[9], float v, int j) {
  if (v > mv[8] || (v == mv[8] && j < mi[8])) {
    float cv = v; int cj = j;
#pragma unroll
    for (int s = 0; s < 9; s++) {
      bool bt = (cv > mv[s]) || (cv == mv[s] && cj < mi[s]);
      float nv = bt ? cv : mv[s]; int ni = bt ? cj : mi[s];
      float ov_ = bt ? mv[s] : cv; int oi = bt ? mi[s] : cj;
      mv[s]=nv; mi[s]=ni; cv=ov_; cj=oi;
    }
  }
}
__device__ __forceinline__ unsigned pkh2(float a, float b) {
  __half ha = __float2half_rn(a), hb = __float2half_rn(b);
  return (unsigned)__half_as_ushort(ha) | ((unsigned)__half_as_ushort(hb) << 16);
}
__device__ __forceinline__ float h2f_lo(unsigned u) {
  return __half2float(__ushort_as_half((unsigned short)(u & 0xFFFF)));
}
__device__ __forceinline__ float h2f_hi(unsigned u) {
  return __half2float(__ushort_as_half((unsigned short)(u >> 16)));
}

// ---------------- K0: fold catt1 into transposed mlp weights ----------------
__global__ void __launch_bounds__(256) prep_kernel(
    const float* __restrict__ mlp_w, const float* __restrict__ catt1) {
  int i = blockIdx.x*256 + threadIdx.x;
  int o = i >> 9, k = i & 511;
  float v = mlp_w[i];
  if (k >= 256) v *= catt1[k-256];
  g_mlpwT[k*256 + o] = v;
}

// ---------------- K1: projections + L2 normalize + layouts ----------------
__global__ void __launch_bounds__(256) proj_kernel(
    const float* __restrict__ feat, const float* __restrict__ Wq,
    const float* __restrict__ Wk,   const float* __restrict__ Wv) {
  __shared__ float xs[64][33];
  __shared__ float ws[96][64];
  __shared__ float outs[96][33];
  __shared__ float scl[2][32];
  int blk = blockIdx.x;
  int b  = blk / 200;
  int n0 = (blk % 200) * 32;
  int t  = threadIdx.x;
  int n  = t & 31, dg = t >> 5;
  float acc[12];
#pragma unroll
  for (int u = 0; u < 12; u++) acc[u] = 0.f;

  for (int c0 = 0; c0 < CC; c0 += 64) {
#pragma unroll
    for (int r = 0; r < 8; r++) {
      int e = t + 256*r; int cl = e >> 5, nn = e & 31;
      xs[cl][nn] = feat[(b*CC + c0 + cl)*HWN + n0 + nn];
    }
#pragma unroll
    for (int r = 0; r < 24; r++) {
      int e = t + 256*r; int cl = e & 63, d = e >> 6;
      const float* Wp = (d < 32) ? Wq : ((d < 64) ? Wk : Wv);
      ws[d][cl] = Wp[(d & 31)*CC + c0 + cl];
    }
    __syncthreads();
#pragma unroll 4
    for (int cl = 0; cl < 64; cl += 4) {
      float x0 = xs[cl][n], x1 = xs[cl+1][n], x2 = xs[cl+2][n], x3 = xs[cl+3][n];
#pragma unroll
      for (int u = 0; u < 12; u++) {
        const float4 w4 = *(const float4*)&ws[dg*12+u][cl];
        acc[u] += w4.x*x0 + w4.y*x1 + w4.z*x2 + w4.w*x3;
      }
    }
    __syncthreads();
  }
#pragma unroll
  for (int u = 0; u < 12; u++) outs[dg*12+u][n] = acc[u];
  __syncthreads();
  if (t < 64) {
    int nn = t & 31, wh = t >> 5;
    float s = 0.f;
#pragma unroll
    for (int d = 0; d < 32; d++) { float v = outs[wh*32+d][nn]; s += v*v; }
    scl[wh][nn] = 1.f / fmaxf(sqrtf(s), 1e-12f);
  }
  __syncthreads();
#pragma unroll
  for (int r = 0; r < 4; r++) {
    int e = t + 256*r; int d = e & 31, nn = e >> 5;
    int nglob = n0 + nn;
    float qv = outs[d][nn] * scl[0][nn];
    g_qn[(b*DD + d)*HWN + nglob] = qv;
    g_qnr[(size_t)(b*HWN + nglob)*DD + d] = qv;
    float kv = outs[32+d][nn] * scl[1][nn];
    g_knr[(size_t)(b*HWN + nglob)*DD + d] = kv;
    __half h0 = __float2half_rn(kv);
    int T = nglob >> 6, jj = nglob & 63;
    int p = d >> 1, slot = d & 1;
    uint16_t* kp = (uint16_t*)g_knph;
    kp[(size_t)(((b*100 + T)*16 + p)*64 + jj)*2 + slot] = __half_as_ushort(h0);
    g_v[(size_t)(b*HWN + nglob)*DD + d] = outs[64+d][nn];
  }
}

// ---------------- K2a: approx w (hi*hi HMMA) -> per-8-group maxes ----------------
__global__ void __launch_bounds__(128) maxw_kernel() {
  __shared__ float qs[32][72];
  __shared__ unsigned bfs[2][16][72];
  int blk = blockIdx.x;
  int b = blk / 400; int rem = blk % 400;
  int split = rem / 100; int i0 = (rem % 100) * 64;
  int t = threadIdx.x;
  int lane = t & 31, w = t >> 5, g = lane >> 2, t4 = lane & 3;
  int ib = w*16;
  int tile0 = split * 25;
  const unsigned* kf = g_knph + (size_t)(b*100 + tile0)*1024;

#pragma unroll
  for (int r = 0; r < 16; r++) {
    int e = t + 128*r; int i = e & 63, d = e >> 6;
    qs[d][i] = g_qn[(b*DD + d)*HWN + i0 + i];
  }
  __syncthreads();

  unsigned Ah[2][4];
#pragma unroll
  for (int c = 0; c < 2; c++) {
    int kb = c*16 + 2*t4;
#pragma unroll
    for (int r = 0; r < 4; r++) {
      int kk = kb + ((r >= 2) ? 8 : 0);
      int ii = ib + g + ((r & 1) ? 8 : 0);
      Ah[c][r] = pkh2(qs[kk][ii], qs[kk+1][ii]);
    }
  }

#pragma unroll
  for (int r = 0; r < 2; r++) {
    int idx = t + 128*r;
    int row = idx >> 4, c16 = idx & 15;
    cpa16(&bfs[0][row][c16*4], kf + row*64 + c16*4);
  }
  CPA_COMMIT();

  for (int jt = 0; jt < 25; jt++) {
    if (jt + 1 < 25) {
      int nb = (jt+1) & 1;
      const unsigned* src = kf + (size_t)(jt+1)*1024;
#pragma unroll
      for (int r = 0; r < 2; r++) {
        int idx = t + 128*r;
        int row = idx >> 4, c16 = idx & 15;
        cpa16(&bfs[nb][row][c16*4], src + row*64 + c16*4);
      }
      CPA_COMMIT();
      CPA_WAIT1();
    } else {
      CPA_WAIT0();
    }
    __syncthreads();
    const unsigned (*hp)[72] = bfs[jt & 1];

    float Cf[8][4];
#pragma unroll
    for (int nf = 0; nf < 8; nf++)
#pragma unroll
      for (int r = 0; r < 4; r++) Cf[nf][r] = 0.f;

#pragma unroll
    for (int c = 0; c < 2; c++) {
#pragma unroll
      for (int nf = 0; nf < 8; nf++) {
        unsigned p1 = hp[c*8 + t4    ][nf*8 + g];
        unsigned p2 = hp[c*8 + t4 + 4][nf*8 + g];
        mma_f16(Cf[nf][0],Cf[nf][1],Cf[nf][2],Cf[nf][3],
                Ah[c][0],Ah[c][1],Ah[c][2],Ah[c][3], p1, p2);
      }
    }
    float gma[8], gmb[8];
#pragma unroll
    for (int nf = 0; nf < 8; nf++) {
      gma[nf] = fmaxf(Cf[nf][0], Cf[nf][1]);
      gmb[nf] = fmaxf(Cf[nf][2], Cf[nf][3]);
    }
#pragma unroll
    for (int nf = 0; nf < 8; nf++) {
      gma[nf] = fmaxf(gma[nf], __shfl_xor_sync(0xffffffffu, gma[nf], 1));
      gma[nf] = fmaxf(gma[nf], __shfl_xor_sync(0xffffffffu, gma[nf], 2));
      gmb[nf] = fmaxf(gmb[nf], __shfl_xor_sync(0xffffffffu, gmb[nf], 1));
      gmb[nf] = fmaxf(gmb[nf], __shfl_xor_sync(0xffffffffu, gmb[nf], 2));
    }
    if (t4 == 0) {
      int tileg = tile0 + jt;
      uint4 pa, pb;
      pa.x = pkh2(gma[0], gma[1]); pa.y = pkh2(gma[2], gma[3]);
      pa.z = pkh2(gma[4], gma[5]); pa.w = pkh2(gma[6], gma[7]);
      pb.x = pkh2(gmb[0], gmb[1]); pb.y = pkh2(gmb[2], gmb[3]);
      pb.z = pkh2(gmb[4], gmb[5]); pb.w = pkh2(gmb[6], gmb[7]);
      size_t ra = (size_t)(b*HWN + i0 + ib + g)*800 + tileg*8;
      size_t rb = (size_t)(b*HWN + i0 + ib + 8 + g)*800 + tileg*8;
      *(uint4*)&g_gmax[ra] = pa;
      *(uint4*)&g_gmax[rb] = pb;
    }
    __syncthreads();
  }
}

// ---------------- K2b: 2 warps/row exact top-9, shared tau ----------------
__global__ void __launch_bounds__(256) topk_kernel() {
  __shared__ float smv[4][12];
  __shared__ int   smi[4][12];
  __shared__ float stau[4][2];
  __shared__ unsigned short glist[8][400];
  int wid = threadIdx.x >> 5;
  int lane = threadIdx.x & 31;
  int pr = wid >> 1, half = wid & 1;
  int grow = blockIdx.x*4 + pr;
  int b = grow / HWN, row = grow % HWN;
  int cand = lane >> 2, qr = lane & 3;

  float qq[8];
  {
    const float* qp = &g_qnr[(size_t)(b*HWN + row)*DD + qr*8];
    float4 a = *(const float4*)qp;
    float4 c = *(const float4*)(qp+4);
    qq[0]=a.x; qq[1]=a.y; qq[2]=a.z; qq[3]=a.w;
    qq[4]=c.x; qq[5]=c.y; qq[6]=c.z; qq[7]=c.w;
  }

  const __half* gmrow = &g_gmax[(size_t)(b*HWN + row)*800 + half*400];
  uint4 ch[2]; bool has[2];
  float m1 = -4.f, m2 = -4.f, m3 = -4.f;
#pragma unroll
  for (int slot = 0; slot < 2; slot++) {
    int c = slot*32 + lane;
    has[slot] = (c < 50);
    if (has[slot]) {
      ch[slot] = *(const uint4*)&gmrow[c*8];
      const unsigned* u = (const unsigned*)&ch[slot];
#pragma unroll
      for (int hh = 0; hh < 4; hh++) {
        float v0 = h2f_lo(u[hh]), v1 = h2f_hi(u[hh]);
        float tlo = fminf(v0, m1); m1 = fmaxf(v0, m1);
        float ulo = fminf(tlo, m2); m2 = fmaxf(tlo, m2);
        m3 = fmaxf(ulo, m3);
        tlo = fminf(v1, m1); m1 = fmaxf(v1, m1);
        ulo = fminf(tlo, m2); m2 = fmaxf(tlo, m2);
        m3 = fmaxf(ulo, m3);
      }
    }
  }
  float tau = -4.f;
#pragma unroll
  for (int rnd = 0; rnd < 9; rnd++) {
    float wm = m1;
#pragma unroll
    for (int s = 16; s > 0; s >>= 1) wm = fmaxf(wm, __shfl_xor_sync(0xffffffffu, wm, s));
    unsigned bal = __ballot_sync(0xffffffffu, m1 == wm);
    int leader = __ffs(bal) - 1;
    if (lane == leader) { m1 = m2; m2 = m3; m3 = -4.f; }
    tau = wm;
  }
  if (lane == 0) stau[pr][half] = tau;
  __syncthreads();
  float thr = fmaxf(stau[pr][0], stau[pr][1]) - 0.002f;

  int cnt = 0;
#pragma unroll
  for (int slot = 0; slot < 2; slot++) {
    unsigned msk = 0;
    if (has[slot]) {
      const unsigned* u = (const unsigned*)&ch[slot];
#pragma unroll
      for (int hh = 0; hh < 4; hh++) {
        if (h2f_lo(u[hh]) >= thr) msk |= 1u << (2*hh);
        if (h2f_hi(u[hh]) >= thr) msk |= 1u << (2*hh+1);
      }
    }
    unsigned lanebal = __ballot_sync(0xffffffffu, msk != 0);
    while (lanebal) {
      int Lb = __ffs(lanebal) - 1; lanebal &= lanebal - 1;
      unsigned gm8 = __shfl_sync(0xffffffffu, msk, Lb);
      int tile = half*50 + slot*32 + Lb;
      while (gm8) {
        int g8 = __ffs(gm8) - 1; gm8 &= gm8 - 1;
        if (lane == 0) glist[wid][cnt] = (unsigned short)(tile*8 + g8);
        cnt++;
      }
    }
  }
  __syncwarp();

  float tv[9]; int ti[9];
#pragma unroll
  for (int s = 0; s < 9; s++) { tv[s] = -4.f; ti[s] = 0x7fffffff; }

  const float* knb = g_knr + (size_t)b*HWN*DD;
  float4 p0, p1;
  if (cnt > 0) {
    int gi0 = glist[wid][0];
    const float* kp = knb + (size_t)(gi0*8 + cand)*DD + qr*8;
    p0 = *(const float4*)kp; p1 = *(const float4*)(kp+4);
  }
  for (int i = 0; i < cnt; i++) {
    float4 c0 = p0, c1 = p1;
    int jb = glist[wid][i]*8;
    if (i + 1 < cnt) {
      int gin = glist[wid][i+1];
      const float* kp = knb + (size_t)(gin*8 + cand)*DD + qr*8;
      p0 = *(const float4*)kp; p1 = *(const float4*)(kp+4);
    }
    float acc = qq[0]*c0.x + qq[1]*c0.y + qq[2]*c0.z + qq[3]*c0.w
              + qq[4]*c1.x + qq[5]*c1.y + qq[6]*c1.z + qq[7]*c1.w;
    acc += __shfl_xor_sync(0xffffffffu, acc, 1);
    acc += __shfl_xor_sync(0xffffffffu, acc, 2);
    float wmax = fmaxf(acc, __shfl_xor_sync(0xffffffffu, acc, 4));
    wmax = fmaxf(wmax, __shfl_xor_sync(0xffffffffu, wmax, 8));
    wmax = fmaxf(wmax, __shfl_xor_sync(0xffffffffu, wmax, 16));
    if (wmax >= tv[8]) {
      unsigned bal = __ballot_sync(0xffffffffu, acc >= tv[8]) & 0x11111111u;
      while (bal) {
        int L = __ffs(bal) - 1; bal &= bal - 1;
        float v = __shfl_sync(0xffffffffu, acc, L);
        ins9t(tv, ti, v, jb + (L >> 2));
      }
    }
  }

  if (half == 1 && lane == 0) {
#pragma unroll
    for (int s = 0; s < 9; s++) { smv[pr][s] = tv[s]; smi[pr][s] = ti[s]; }
  }
  __syncthreads();
  if (half == 0) {
#pragma unroll
    for (int s = 0; s < 9; s++) ins9t(tv, ti, smv[pr][s], smi[pr][s]);
    if (lane == 0) {
      size_t base = (size_t)(b*HWN + row)*12;
#pragma unroll
      for (int s = 0; s < 9; s++) { g_pval[base+s] = tv[s]; g_pidx[base+s] = ti[s]; }
    }
  }
}

// ---------------- K3: post (single sorted list per row) ----------------
__global__ void __launch_bounds__(256) post_kernel(
    const float* __restrict__ adw, const float* __restrict__ adb,
    const float* __restrict__ pw1, const float* __restrict__ pw2,
    const float* __restrict__ back_w, const float* __restrict__ catt) {
  __shared__ float lv2[32][12];
  __shared__ int   li2[32][12];
  __shared__ float w1s[162];
  __shared__ float w2s[162];
  __shared__ float wfin_s[32][12];
  __shared__ int   idx_s[32][12];
  __shared__ float ovs[32][36];
  int blk = blockIdx.x;
  int b = blk / 200;
  int row0 = (blk % 200) * 32;
  int t = threadIdx.x;

  float4 bw[8];
#pragma unroll
  for (int r = 0; r < 8; r++) bw[r] = *(const float4*)&back_w[t*DD + r*4];
  float cattc = catt[t];
  if (t < 162) { w1s[t] = pw1[t]; w2s[t] = pw2[t]; }

#pragma unroll
  for (int r = 0; r < 2; r++) {
    int e = t + 256*r;
    if (e < 384) {
      int row = e / 12, q = e % 12;
      size_t gbase = (size_t)(b*HWN + row0 + row)*12 + q;
      lv2[row][q] = g_pval[gbase];
      li2[row][q] = g_pidx[gbase];
    }
  }
  __syncthreads();

  if (t < 32) {
    float adwv = adw[0], adbv = adb[0];
    float xa[9], pos[9];
#pragma unroll
    for (int p = 0; p < 9; p++) { xa[p] = lv2[t][p]*adwv + adbv; pos[p] = fmaxf(xa[p], 0.f); }
    float hdn[18];
#pragma unroll
    for (int q = 0; q < 18; q++) {
      float s = 0.f;
#pragma unroll
      for (int p = 0; p < 9; p++) s += w1s[q*9+p]*pos[p];
      hdn[q] = fmaxf(s, 0.f);
    }
    float z[9]; float zmax = -1e30f;
#pragma unroll
    for (int p = 0; p < 9; p++) { z[p] = (xa[p] > 0.f) ? xa[p] : -100000.0f; zmax = fmaxf(zmax, z[p]); }
    float es[9]; float esum = 0.f;
#pragma unroll
    for (int p = 0; p < 9; p++) { es[p] = expf(z[p]-zmax); esum += es[p]; }
    float inv = 1.f/esum;
#pragma unroll
    for (int p = 0; p < 9; p++) {
      float s = 0.f;
#pragma unroll
      for (int q = 0; q < 18; q++) s += w2s[p*18+q]*hdn[q];
      float msk = 1.f/(1.f+expf(-s));
      wfin_s[t][p] = es[p]*inv*msk;
      idx_s[t][p]  = li2[t][p];
    }
  }
  __syncthreads();

  {
    int row = t >> 3, dq = t & 7;
    float4 acc = make_float4(0.f, 0.f, 0.f, 0.f);
#pragma unroll
    for (int p = 0; p < 9; p++) {
      float wv = wfin_s[row][p];
      int j = idx_s[row][p];
      float4 v4 = *(const float4*)&g_v[((size_t)b*HWN + j)*DD + dq*4];
      acc.x += wv*v4.x; acc.y += wv*v4.y; acc.z += wv*v4.z; acc.w += wv*v4.w;
    }
    *(float4*)&ovs[row][dq*4] = acc;
  }
  __syncthreads();

  float* dst = &g_ovb[((size_t)b*CC + t)*HWN + row0];
#pragma unroll
  for (int r4 = 0; r4 < 8; r4++) {
    float4 o4;
    float* o = (float*)&o4;
#pragma unroll
    for (int u = 0; u < 4; u++) {
      int row = r4*4 + u;
      float acc = 0.f;
#pragma unroll
      for (int d4 = 0; d4 < 8; d4++) {
        float4 v4 = *(const float4*)&ovs[row][d4*4];
        acc += bw[d4].x*v4.x + bw[d4].y*v4.y + bw[d4].z*v4.z + bw[d4].w*v4.w;
      }
      o[u] = acc * cattc;
    }
    *(float4*)&dst[r4*4] = o4;
  }
}

// ---------------- K4: mlp GEMM (3xTF32 mma.sync, cp.async) ----------------
__global__ void __launch_bounds__(128) mlp_kernel(
    const float* __restrict__ feat, const float* __restrict__ mlp_b,
    const float* __restrict__ mlp_gamma, const float* __restrict__ mlp_beta,
    float* __restrict__ xout) {
  __shared__ float a_s[2][32][72];
  __shared__ float b_s[2][32][72];
  int blk = blockIdx.x;
  int b = blk / 400; int rem = blk % 400;
  int o0 = (rem / 100) * 64;
  int n0 = (rem % 100) * 64;
  int t = threadIdx.x;
  int w = t >> 5, lane = t & 31, g = lane >> 2, t4 = lane & 3;
  int ol = w*16;

  float Cf[8][4];
#pragma unroll
  for (int nf = 0; nf < 8; nf++)
#pragma unroll
    for (int r = 0; r < 4; r++) Cf[nf][r] = 0.f;

  const float* bbase = &g_ovb[(size_t)b*CC*HWN];
  const float* fbase = &feat[(size_t)b*CC*HWN];

#pragma unroll
  for (int r = 0; r < 4; r++) {
    int q = t + 128*r; int kk = q >> 4; int xx = (q & 15)*4;
    cpa16(&a_s[0][kk][xx], &g_mlpwT[kk*256 + o0 + xx]);
    cpa16(&b_s[0][kk][xx], bbase + (size_t)kk*HWN + n0 + xx);
  }
  CPA_COMMIT();

  for (int kt = 0; kt < 16; kt++) {
    if (kt + 1 < 16) {
      int k1 = (kt+1)*32; int buf = (kt+1) & 1;
      const float* srcB = (k1 < 256) ? (bbase + (size_t)k1*HWN)
                                     : (fbase + (size_t)(k1-256)*HWN);
#pragma unroll
      for (int r = 0; r < 4; r++) {
        int q = t + 128*r; int kk = q >> 4; int xx = (q & 15)*4;
        cpa16(&a_s[buf][kk][xx], &g_mlpwT[(k1+kk)*256 + o0 + xx]);
        cpa16(&b_s[buf][kk][xx], srcB + (size_t)kk*HWN + n0 + xx);
      }
      CPA_COMMIT();
      CPA_WAIT1();
    } else {
      CPA_WAIT0();
    }
    __syncthreads();
    int buf = kt & 1;
    const float (*ab)[72] = a_s[buf];
    const float (*bb)[72] = b_s[buf];

    unsigned Ah[4][4], Al[4][4];
#pragma unroll
    for (int k8 = 0; k8 < 4; k8++) {
      int kb = k8*8;
      split2(ab[kb+t4  ][ol+g  ], Ah[k8][0], Al[k8][0]);
      split2(ab[kb+t4  ][ol+g+8], Ah[k8][1], Al[k8][1]);
      split2(ab[kb+t4+4][ol+g  ], Ah[k8][2], Al[k8][2]);
      split2(ab[kb+t4+4][ol+g+8], Ah[k8][3], Al[k8][3]);
    }
#pragma unroll
    for (int k8 = 0; k8 < 4; k8++) {
      int kk = k8*8;
#pragma unroll
      for (int nf = 0; nf < 8; nf++) {
        unsigned Bh0, Bl0, Bh1, Bl1;
        split2(bb[kk+t4  ][nf*8+g], Bh0, Bl0);
        split2(bb[kk+t4+4][nf*8+g], Bh1, Bl1);
        mma_tf32(Cf[nf][0],Cf[nf][1],Cf[nf][2],Cf[nf][3],
                 Al[k8][0],Al[k8][1],Al[k8][2],Al[k8][3], Bh0,Bh1);
        mma_tf32(Cf[nf][0],Cf[nf][1],Cf[nf][2],Cf[nf][3],
                 Ah[k8][0],Ah[k8][1],Ah[k8][2],Ah[k8][3], Bl0,Bl1);
        mma_tf32(Cf[nf][0],Cf[nf][1],Cf[nf][2],Cf[nf][3],
                 Ah[k8][0],Ah[k8][1],Ah[k8][2],Ah[k8][3], Bh0,Bh1);
      }
    }
    __syncthreads();
  }
  const float bnadj = rsqrtf(1.0f + 1e-5f);
  int oa = o0 + ol + g;
  int ob = oa + 8;
  float ga  = mlp_gamma[oa]*bnadj, ba = mlp_beta[oa], mba = mlp_b[oa];
  float gb2 = mlp_gamma[ob]*bnadj, bb2 = mlp_beta[ob], mbb = mlp_b[ob];
#pragma unroll
  for (int nf = 0; nf < 8; nf++) {
    int nc = n0 + nf*8 + 2*t4;
    float2 ra, rb;
    ra.x = fmaxf((Cf[nf][0]+mba)*ga + ba, 0.f);
    ra.y = fmaxf((Cf[nf][1]+mba)*ga + ba, 0.f);
    rb.x = fmaxf((Cf[nf][2]+mbb)*gb2 + bb2, 0.f);
    rb.y = fmaxf((Cf[nf][3]+mbb)*gb2 + bb2, 0.f);
    *(float2*)&xout[((size_t)b*CC + oa)*HWN + nc] = ra;
    *(float2*)&xout[((size_t)b*CC + ob)*HWN + nc] = rb;
  }
}

// ---------------- K5: dsn head ----------------
__global__ void __launch_bounds__(256) dsn_kernel(
    const float* __restrict__ dsn_w, const float* __restrict__ dsn_b,
    const float* __restrict__ dsn_g, const float* __restrict__ dsn_beta,
    const float* __restrict__ x, float* __restrict__ r0) {
  __shared__ float ws[256];
  __shared__ float s2[2][128];
  int blk = blockIdx.x;
  int b  = blk / 50;
  int n0 = (blk % 50) * 128;
  int t  = threadIdx.x;
  ws[t] = dsn_w[t];
  __syncthreads();
  int nl = t & 127, half = t >> 7;
  int n = n0 + nl;
  float acc = 0.f;
  int obase = half*128;
#pragma unroll 8
  for (int o = 0; o < 128; o++) acc += ws[obase+o]*x[(b*CC+obase+o)*HWN + n];
  s2[half][nl] = acc;
  __syncthreads();
  if (t < 128) {
    float a = s2[0][t] + s2[1][t];
    float g = dsn_g[0]*rsqrtf(1.0f+1e-5f);
    r0[b*HWN + n0 + t] = fmaxf((a + dsn_b[0])*g + dsn_beta[0], 0.f);
  }
}

// ---------------- launch ----------------
extern "C" void kernel_launch(void* const* d_in, const int* in_sizes, int n_in,
                              void* d_out, int out_size) {
  const float* feat    = (const float*)d_in[0];
  const float* Wq      = (const float*)d_in[1];
  const float* Wk      = (const float*)d_in[2];
  const float* Wv      = (const float*)d_in[3];
  const float* adw     = (const float*)d_in[4];
  const float* adb     = (const float*)d_in[5];
  const float* pw1     = (const float*)d_in[6];
  const float* pw2     = (const float*)d_in[7];
  const float* backw   = (const float*)d_in[8];
  const float* catt    = (const float*)d_in[9];
  const float* catt1   = (const float*)d_in[10];
  const float* mlpw    = (const float*)d_in[11];
  const float* mlpb    = (const float*)d_in[12];
  const float* mlpg    = (const float*)d_in[13];
  const float* mlpbeta = (const float*)d_in[14];
  const float* dsnw    = (const float*)d_in[15];
  const float* dsnb    = (const float*)d_in[16];
  const float* dsng    = (const float*)d_in[17];
  const float* dsnbeta = (const float*)d_in[18];
  float* out = (float*)d_out;

  // slot 3 (ncu capture) = maxw_kernel this round (prep launched twice,
  // idempotent, to shift slots; ~2us cost for the profile visibility)
  proj_kernel<<<400, 256>>>(feat, Wq, Wk, Wv);
  prep_kernel<<<512, 256>>>(mlpw, catt1);
  prep_kernel<<<512, 256>>>(mlpw, catt1);
  maxw_kernel<<<800, 128>>>();
  topk_kernel<<<3200, 256>>>();
  post_kernel<<<400, 256>>>(adw, adb, pw1, pw2, backw, catt);
  mlp_kernel<<<800, 128>>>(feat, mlpb, mlpg, mlpbeta, out);
  dsn_kernel<<<100, 256>>>(dsnw, dsnb, dsng, dsnbeta, out, out + BB*CC*HWN);
}